// round 11
// baseline (speedup 1.0000x reference)
#include <cuda_runtime.h>
#include <cstdint>
#include <cstddef>

#define NB    64
#define LMAX  4096
#define DD    128
#define RLK   64
#define RDR   16
#define NCH   16
#define TILE_L 256
#define LN_EPS 1e-5f

typedef unsigned long long ull;

__device__ float g_Up[NB * NCH * RLK * RDR];   // 4 MB partial-U scratch
__device__ float g_U[NB * 1024];
__device__ float g_z[NB * 512];
__device__ float g_h[NB * 512];
__device__ float g_r[NB * 512];

__device__ __forceinline__ ull dup2(float x) {
    ull r; asm("mov.b64 %0, {%1, %1};" : "=l"(r) : "f"(x)); return r;
}
__device__ __forceinline__ void fma2(ull& d, ull a, ull b) {
    asm("fma.rn.f32x2 %0, %1, %2, %0;" : "+l"(d) : "l"(a), "l"(b));
}
__device__ __forceinline__ ull add2(ull a, ull b) {
    ull r; asm("add.rn.f32x2 %0, %1, %2;" : "=l"(r) : "l"(a), "l"(b)); return r;
}

// mask modes: 0 = u8/bool, 1 = int32 (0/1), 2 = float32 (0.0/1.0)
__device__ __forceinline__ float mask_val(const void* mp, int mode, int idx) {
    if (mode == 0) return ((const unsigned char*)mp)[idx] ? 1.0f : 0.0f;
    if (mode == 1) return ((const int*)mp)[idx] ? 1.0f : 0.0f;
    return ((const float*)mp)[idx];
}

// ---------------------------------------------------------------------------
// Kernel 1 (unchanged): fused masked-emb -> Y = X @ B_c -> U_partial
// ---------------------------------------------------------------------------
__global__ void __launch_bounds__(256, 3) k1_kernel(
    const float* __restrict__ emb, const void* __restrict__ maskp,
    const float* __restrict__ Bc,  const float* __restrict__ Ac)
{
    extern __shared__ float sm[];
    float* sBc  = sm;            // [128][16]   2048 floats
    float* sY   = sm + 2048;     // [256][18]   4608
    float* sRed = sm + 6656;     // [4][64*18]  4608  -> 11264 floats = 45056 B

    const int tid = threadIdx.x;
    const int b   = blockIdx.y;
    const int l0  = blockIdx.x * TILE_L;
    const unsigned char* mb = (const unsigned char*)maskp;

    int det = (tid < 64) ? (int)mb[(size_t)LMAX * tid + 1] : 0;

    {
        const float4* s = (const float4*)Bc;
        float4* d4 = (float4*)sBc;
        d4[tid] = s[tid]; d4[tid + 256] = s[tid + 256];
    }

    int any_u8 = __syncthreads_or(det);
    const int mode = any_u8 ? 0 : (mb[3] ? 2 : 1);

    const int r = tid;
    const float m = mask_val(maskp, mode, b * LMAX + l0 + r);
    float* gup = g_Up + ((size_t)(b * NCH + blockIdx.x)) * 1024;

    int any = __syncthreads_or(m != 0.0f);
    if (!any) {
        ((float4*)gup)[tid] = make_float4(0.f, 0.f, 0.f, 0.f);
        return;
    }

    ull acc[8];
    #pragma unroll
    for (int q = 0; q < 8; ++q) acc[q] = 0ull;

    if (m != 0.0f) {
        const float4* gx = (const float4*)(emb + ((size_t)b * LMAX + l0 + r) * DD);
        #pragma unroll 2
        for (int i = 0; i < 32; ++i) {
            float4 v = gx[i];
            v.x *= m; v.y *= m; v.z *= m; v.w *= m;
            float vs[4] = {v.x, v.y, v.z, v.w};
            #pragma unroll
            for (int j = 0; j < 4; ++j) {
                const ulonglong2* bc = (const ulonglong2*)(sBc + (i * 4 + j) * RDR);
                ulonglong2 p0 = bc[0], p1 = bc[1], p2 = bc[2], p3 = bc[3];
                ull x = dup2(vs[j]);
                fma2(acc[0], x, p0.x); fma2(acc[1], x, p0.y);
                fma2(acc[2], x, p1.x); fma2(acc[3], x, p1.y);
                fma2(acc[4], x, p2.x); fma2(acc[5], x, p2.y);
                fma2(acc[6], x, p3.x); fma2(acc[7], x, p3.y);
            }
        }
    }
    {
        float* y = sY + r * 18;
        #pragma unroll
        for (int q = 0; q < 8; ++q) *(ull*)(y + 2 * q) = acc[q];
    }
    __syncthreads();

    {
        const int kq  = tid & 15;
        const int rg2 = (tid >> 4) & 3;
        const int ls  = tid >> 6;
        ull c[4][2];
        #pragma unroll
        for (int i = 0; i < 4; ++i) { c[i][0] = 0ull; c[i][1] = 0ull; }

        const float* ar = Ac + (size_t)(l0 + ls * 64) * RLK + kq * 4;
        const float* yr = sY + (ls * 64) * 18 + rg2 * 4;
        #pragma unroll 8
        for (int l = 0; l < 64; ++l) {
            float4 a4 = __ldg((const float4*)(ar + l * RLK));
            ull y0 = *(const ull*)(yr + l * 18);
            ull y1 = *(const ull*)(yr + l * 18 + 2);
            float as[4] = {a4.x, a4.y, a4.z, a4.w};
            #pragma unroll
            for (int i = 0; i < 4; ++i) {
                ull aa = dup2(as[i]);
                fma2(c[i][0], aa, y0);
                fma2(c[i][1], aa, y1);
            }
        }
        #pragma unroll
        for (int i = 0; i < 4; ++i) {
            float* p = sRed + ls * 1152 + (kq * 4 + i) * 18 + rg2 * 4;
            *(ull*)p       = c[i][0];
            *(ull*)(p + 2) = c[i][1];
        }
    }
    __syncthreads();

    {
        const int k  = tid >> 2;
        const int rq = tid & 3;
        ull s0 = 0ull, s1 = 0ull;
        #pragma unroll
        for (int s = 0; s < 4; ++s) {
            const float* p = sRed + s * 1152 + k * 18 + rq * 4;
            s0 = add2(s0, *(const ull*)p);
            s1 = add2(s1, *(const ull*)(p + 2));
        }
        *(ull*)(gup + k * 16 + rq * 4)     = s0;
        *(ull*)(gup + k * 16 + rq * 4 + 2) = s1;
    }
}

// ---------------------------------------------------------------------------
// k2u: reduce 16 chunk-partials -> g_U[64][1024]. grid 64, 256 threads.
// ---------------------------------------------------------------------------
__global__ void __launch_bounds__(256) k2u_kernel()
{
    const int tid = threadIdx.x;
    const int b   = blockIdx.x;
    const float4* p = (const float4*)(g_Up + (size_t)b * NCH * 1024) + tid;
    float4 v[NCH];
    #pragma unroll
    for (int ch = 0; ch < NCH; ++ch) v[ch] = p[ch * 256];
    float4 s = v[0];
    #pragma unroll
    for (int ch = 1; ch < NCH; ++ch) {
        s.x += v[ch].x; s.y += v[ch].y; s.z += v[ch].z; s.w += v[ch].w;
    }
    ((float4*)(g_U + (size_t)b * 1024))[tid] = s;
}

// ---------------------------------------------------------------------------
// gemm: out[b, j] = sum_i in[b, i] * W[i, j] (+ bias[j])
// grid 64 j-tiles of 8 columns, 512 threads = 2 i-halves x 64 b x 4 j-pairs.
// Each weight column is read by exactly ONE block (weights read once chip-wide).
// ---------------------------------------------------------------------------
template<int K, bool BIAS>
__global__ void __launch_bounds__(512) gemm_kernel(
    const float* __restrict__ in, const float* __restrict__ W,
    const float* __restrict__ bias, float* __restrict__ out)
{
    __shared__ ull sP[256];

    const int tid  = threadIdx.x;
    const int ih   = tid >> 8;         // i-half
    const int rem  = tid & 255;
    const int b    = rem >> 2;         // batch 0..63
    const int jh   = rem & 3;          // j-pair 0..3
    const int joff = blockIdx.x * 8 + jh * 2;

    constexpr int KH = K / 2;
    const float* inb = in + (size_t)b * K + ih * KH;
    const float* wp  = W + (size_t)(ih * KH) * 512 + joff;

    ull acc = 0ull;
    #pragma unroll 2
    for (int i0 = 0; i0 < KH; i0 += 16) {
        float4 uv[4]; ull hv[16];
        #pragma unroll
        for (int q = 0; q < 4; ++q)
            uv[q] = *(const float4*)(inb + i0 + q * 4);
        #pragma unroll
        for (int k = 0; k < 16; ++k)
            hv[k] = *(const ull*)(wp + (size_t)(i0 + k) * 512);
        float us[16] = {uv[0].x, uv[0].y, uv[0].z, uv[0].w,
                        uv[1].x, uv[1].y, uv[1].z, uv[1].w,
                        uv[2].x, uv[2].y, uv[2].z, uv[2].w,
                        uv[3].x, uv[3].y, uv[3].z, uv[3].w};
        #pragma unroll
        for (int k = 0; k < 16; ++k)
            fma2(acc, dup2(us[k]), hv[k]);
    }

    if (ih == 1) sP[rem] = acc;
    __syncthreads();
    if (ih == 0) {
        acc = add2(acc, sP[rem]);
        if (BIAS) acc = add2(acc, *(const ull*)(bias + joff));
        *(ull*)(out + (size_t)b * 512 + joff) = acc;
    }
}

// ---------------------------------------------------------------------------
// k2ln: per-batch LayerNorm + ReLU: g_h -> g_r. grid 64, 512 threads.
// ---------------------------------------------------------------------------
__global__ void __launch_bounds__(512) k2ln_kernel(
    const float* __restrict__ lnw, const float* __restrict__ lnb)
{
    __shared__ float sWr[32];
    __shared__ float sStat[2];

    const int tid = threadIdx.x;
    const int b   = blockIdx.x;

    float hval = g_h[(size_t)b * 512 + tid];
    float ssum = hval, ssq = hval * hval;
    #pragma unroll
    for (int off = 16; off > 0; off >>= 1) {
        ssum += __shfl_xor_sync(0xffffffffu, ssum, off);
        ssq  += __shfl_xor_sync(0xffffffffu, ssq,  off);
    }
    if ((tid & 31) == 0) { sWr[tid >> 5] = ssum; sWr[16 + (tid >> 5)] = ssq; }
    __syncthreads();
    if (tid == 0) {
        float S = 0.f, Q = 0.f;
        #pragma unroll
        for (int w = 0; w < 16; ++w) { S += sWr[w]; Q += sWr[16 + w]; }
        float mu  = S * (1.0f / 512.0f);
        float var = Q * (1.0f / 512.0f) - mu * mu;
        sStat[0] = mu;
        sStat[1] = rsqrtf(var + LN_EPS);
    }
    __syncthreads();
    float hn = (hval - sStat[0]) * sStat[1] * lnw[tid] + lnb[tid];
    g_r[(size_t)b * 512 + tid] = fmaxf(hn, 0.0f);
}

extern "C" void kernel_launch(void* const* d_in, const int* in_sizes, int n_in,
                              void* d_out, int out_size)
{
    (void)in_sizes; (void)n_in; (void)out_size;
    cudaFuncSetAttribute(k1_kernel, cudaFuncAttributeMaxDynamicSharedMemorySize, 45056);

    const float* emb  = (const float*)d_in[0];
    const void*  mskp = d_in[1];
    const float* Bc   = (const float*)d_in[2];
    const float* Ac   = (const float*)d_in[3];
    const float* Hc   = (const float*)d_in[4];
    const float* W1   = (const float*)d_in[5];
    const float* b1   = (const float*)d_in[6];
    const float* lnw  = (const float*)d_in[7];
    const float* lnb  = (const float*)d_in[8];
    const float* W2   = (const float*)d_in[9];
    const float* b2   = (const float*)d_in[10];
    float* out = (float*)d_out;

    float* gU = nullptr; float* gz = nullptr; float* gh = nullptr; float* gr = nullptr;
    cudaGetSymbolAddress((void**)&gU, g_U);
    cudaGetSymbolAddress((void**)&gz, g_z);
    cudaGetSymbolAddress((void**)&gh, g_h);
    cudaGetSymbolAddress((void**)&gr, g_r);

    dim3 g1(NCH, NB);
    k1_kernel<<<g1, 256, 45056>>>(emb, mskp, Bc, Ac);
    k2u_kernel<<<NB, 256>>>();
    gemm_kernel<1024, false><<<64, 512>>>(gU, Hc, nullptr, gz);
    gemm_kernel<512,  true ><<<64, 512>>>(gz, W1, b1, gh);
    k2ln_kernel<<<NB, 512>>>(lnw, lnb);
    gemm_kernel<512,  true ><<<64, 512>>>(gr, W2, b2, out);
}

// round 14
// speedup vs baseline: 1.4625x; 1.4625x over previous
#include <cuda_runtime.h>
#include <cstdint>
#include <cstddef>

#define NB    64
#define LMAX  4096
#define DD    128
#define RLK   64
#define RDR   16
#define NCH   16
#define TILE_L 256
#define LN_EPS 1e-5f
#define MBLOCKS 128

typedef unsigned long long ull;

__device__ float g_Up[NB * NCH * RLK * RDR];   // 4 MB partial-U scratch
__device__ float g_U [NB * 1024];
__device__ float g_pz[4 * NB * 512];
__device__ float g_ph[4 * NB * 512];
__device__ float g_po[4 * NB * 512];
__device__ float g_r [NB * 512];
__device__ unsigned g_cnt = 0;
__device__ unsigned g_gen = 0;

__device__ __forceinline__ ull dup2(float x) {
    ull r; asm("mov.b64 %0, {%1, %1};" : "=l"(r) : "f"(x)); return r;
}
__device__ __forceinline__ void fma2(ull& d, ull a, ull b) {
    asm("fma.rn.f32x2 %0, %1, %2, %0;" : "+l"(d) : "l"(a), "l"(b));
}
__device__ __forceinline__ ull add2(ull a, ull b) {
    ull r; asm("add.rn.f32x2 %0, %1, %2;" : "=l"(r) : "l"(a), "l"(b)); return r;
}

// mask modes: 0 = u8/bool, 1 = int32 (0/1), 2 = float32 (0.0/1.0)
__device__ __forceinline__ float mask_val(const void* mp, int mode, int idx) {
    if (mode == 0) return ((const unsigned char*)mp)[idx] ? 1.0f : 0.0f;
    if (mode == 1) return ((const int*)mp)[idx] ? 1.0f : 0.0f;
    return ((const float*)mp)[idx];
}

// ---------------------------------------------------------------------------
// Kernel 1 (unchanged): fused masked-emb -> Y = X @ B_c -> U_partial
// ---------------------------------------------------------------------------
__global__ void __launch_bounds__(256, 3) k1_kernel(
    const float* __restrict__ emb, const void* __restrict__ maskp,
    const float* __restrict__ Bc,  const float* __restrict__ Ac)
{
    extern __shared__ float sm[];
    float* sBc  = sm;            // [128][16]   2048 floats
    float* sY   = sm + 2048;     // [256][18]   4608
    float* sRed = sm + 6656;     // [4][64*18]  4608  -> 11264 floats = 45056 B

    const int tid = threadIdx.x;
    const int b   = blockIdx.y;
    const int l0  = blockIdx.x * TILE_L;
    const unsigned char* mb = (const unsigned char*)maskp;

    int det = (tid < 64) ? (int)mb[(size_t)LMAX * tid + 1] : 0;

    {
        const float4* s = (const float4*)Bc;
        float4* d4 = (float4*)sBc;
        d4[tid] = s[tid]; d4[tid + 256] = s[tid + 256];
    }

    int any_u8 = __syncthreads_or(det);
    const int mode = any_u8 ? 0 : (mb[3] ? 2 : 1);

    const int r = tid;
    const float m = mask_val(maskp, mode, b * LMAX + l0 + r);
    float* gup = g_Up + ((size_t)(b * NCH + blockIdx.x)) * 1024;

    int any = __syncthreads_or(m != 0.0f);
    if (!any) {
        ((float4*)gup)[tid] = make_float4(0.f, 0.f, 0.f, 0.f);
        return;
    }

    ull acc[8];
    #pragma unroll
    for (int q = 0; q < 8; ++q) acc[q] = 0ull;

    if (m != 0.0f) {
        const float4* gx = (const float4*)(emb + ((size_t)b * LMAX + l0 + r) * DD);
        #pragma unroll 2
        for (int i = 0; i < 32; ++i) {
            float4 v = gx[i];
            v.x *= m; v.y *= m; v.z *= m; v.w *= m;
            float vs[4] = {v.x, v.y, v.z, v.w};
            #pragma unroll
            for (int j = 0; j < 4; ++j) {
                const ulonglong2* bc = (const ulonglong2*)(sBc + (i * 4 + j) * RDR);
                ulonglong2 p0 = bc[0], p1 = bc[1], p2 = bc[2], p3 = bc[3];
                ull x = dup2(vs[j]);
                fma2(acc[0], x, p0.x); fma2(acc[1], x, p0.y);
                fma2(acc[2], x, p1.x); fma2(acc[3], x, p1.y);
                fma2(acc[4], x, p2.x); fma2(acc[5], x, p2.y);
                fma2(acc[6], x, p3.x); fma2(acc[7], x, p3.y);
            }
        }
    }
    {
        float* y = sY + r * 18;
        #pragma unroll
        for (int q = 0; q < 8; ++q) *(ull*)(y + 2 * q) = acc[q];
    }
    __syncthreads();

    {
        const int kq  = tid & 15;
        const int rg2 = (tid >> 4) & 3;
        const int ls  = tid >> 6;
        ull c[4][2];
        #pragma unroll
        for (int i = 0; i < 4; ++i) { c[i][0] = 0ull; c[i][1] = 0ull; }

        const float* ar = Ac + (size_t)(l0 + ls * 64) * RLK + kq * 4;
        const float* yr = sY + (ls * 64) * 18 + rg2 * 4;
        #pragma unroll 8
        for (int l = 0; l < 64; ++l) {
            float4 a4 = __ldg((const float4*)(ar + l * RLK));
            ull y0 = *(const ull*)(yr + l * 18);
            ull y1 = *(const ull*)(yr + l * 18 + 2);
            float as[4] = {a4.x, a4.y, a4.z, a4.w};
            #pragma unroll
            for (int i = 0; i < 4; ++i) {
                ull aa = dup2(as[i]);
                fma2(c[i][0], aa, y0);
                fma2(c[i][1], aa, y1);
            }
        }
        #pragma unroll
        for (int i = 0; i < 4; ++i) {
            float* p = sRed + ls * 1152 + (kq * 4 + i) * 18 + rg2 * 4;
            *(ull*)p       = c[i][0];
            *(ull*)(p + 2) = c[i][1];
        }
    }
    __syncthreads();

    {
        const int k  = tid >> 2;
        const int rq = tid & 3;
        ull s0 = 0ull, s1 = 0ull;
        #pragma unroll
        for (int s = 0; s < 4; ++s) {
            const float* p = sRed + s * 1152 + k * 18 + rq * 4;
            s0 = add2(s0, *(const ull*)p);
            s1 = add2(s1, *(const ull*)(p + 2));
        }
        *(ull*)(gup + k * 16 + rq * 4)     = s0;
        *(ull*)(gup + k * 16 + rq * 4 + 2) = s1;
    }
}

// ---------------------------------------------------------------------------
// Grid-wide sense-reversal barrier (all MBLOCKS blocks co-resident).
// ---------------------------------------------------------------------------
__device__ __forceinline__ void grid_bar() {
    __threadfence();
    __syncthreads();
    if (threadIdx.x == 0) {
        unsigned gen = *(volatile unsigned*)&g_gen;
        if (atomicAdd(&g_cnt, 1u) == MBLOCKS - 1) {
            g_cnt = 0;
            __threadfence();
            atomicExch(&g_gen, gen + 1u);
        } else {
            while (*(volatile unsigned*)&g_gen == gen) __nanosleep(32);
        }
        __threadfence();
    }
    __syncthreads();
}

// ---------------------------------------------------------------------------
// GEMM stage: part[ip][b][j] = sum_{i in ip-slice} in[b][i] * W[i][j]
// 128 blocks = 32 j-tiles (16 cols) x 4 i-splits (ip). Threads: jq(4) x bg(16)
// x is(8). Each thread accumulates an 8-i sub-slice; the 8 is-slices are then
// REDUCED through shared memory before the single write to part (R13 fix).
// Input chunk (64 b x 64 i) staged in smem [b][65]; NP>1 sums NP partials.
// sBuf: >= 8192 floats (32 KB), used as sIn (4160 floats) then as sAcc.
// ---------------------------------------------------------------------------
template<int K, int NP>
__device__ __forceinline__ void gemm_stage(
    const float* __restrict__ in, const float* __restrict__ W,
    float* __restrict__ part, float* sBuf)
{
    float* sIn = sBuf;
    const int tid = threadIdx.x;
    const int j0  = (blockIdx.x >> 2) * 16;
    const int ip  = blockIdx.x & 3;
    constexpr int IPB = K / 4;
    constexpr int NCHUNK = IPB / 64;

    const int jq = tid & 3;
    const int bg = (tid >> 2) & 15;
    const int is = tid >> 6;          // 0..7
    const int rem = tid & 63;         // = bg*4 + jq

    ull acc[4][2];
#pragma unroll
    for (int i = 0; i < 4; ++i) { acc[i][0] = 0ull; acc[i][1] = 0ull; }

    const int sb  = tid >> 3;
    const int siq = (tid & 7) * 8;

#pragma unroll
    for (int c = 0; c < NCHUNK; ++c) {
        const int gi0 = ip * IPB + c * 64;
        __syncthreads();
        {
            float4 a, b4;
            if (NP == 1) {
                const float* p = in + (size_t)sb * K + gi0 + siq;
                a  = *(const float4*)p;
                b4 = *(const float4*)(p + 4);
            } else {
                a = make_float4(0.f, 0.f, 0.f, 0.f);
                b4 = make_float4(0.f, 0.f, 0.f, 0.f);
#pragma unroll
                for (int p = 0; p < NP; ++p) {
                    const float* q = in + ((size_t)p * 64 + sb) * K + gi0 + siq;
                    float4 x = *(const float4*)q;
                    float4 y = *(const float4*)(q + 4);
                    a.x += x.x; a.y += x.y; a.z += x.z; a.w += x.w;
                    b4.x += y.x; b4.y += y.y; b4.z += y.z; b4.w += y.w;
                }
            }
            float* s = sIn + sb * 65 + siq;
            s[0] = a.x;  s[1] = a.y;  s[2] = a.z;  s[3] = a.w;
            s[4] = b4.x; s[5] = b4.y; s[6] = b4.z; s[7] = b4.w;
        }
        __syncthreads();
        const float* wp  = W + (size_t)(gi0 + is * 8) * 512 + j0 + jq * 4;
        const float* ib0 = sIn + (bg * 4) * 65 + is * 8;
#pragma unroll
        for (int k = 0; k < 8; ++k) {
            ulonglong2 w = *(const ulonglong2*)(wp + (size_t)k * 512);
            float i0v = ib0[k];
            float i1v = ib0[65 + k];
            float i2v = ib0[130 + k];
            float i3v = ib0[195 + k];
            ull x0 = dup2(i0v), x1 = dup2(i1v), x2 = dup2(i2v), x3 = dup2(i3v);
            fma2(acc[0][0], x0, w.x); fma2(acc[0][1], x0, w.y);
            fma2(acc[1][0], x1, w.x); fma2(acc[1][1], x1, w.y);
            fma2(acc[2][0], x2, w.x); fma2(acc[2][1], x2, w.y);
            fma2(acc[3][0], x3, w.x); fma2(acc[3][1], x3, w.y);
        }
    }

    // ---- reduce the 8 is-slices (this was missing in R11) ----
    __syncthreads();                      // done reading sIn; reuse as sAcc
    ull* sAcc = (ull*)sBuf;               // [8 q][8 is][64 rem] = 4096 ull = 32 KB
#pragma unroll
    for (int i = 0; i < 4; ++i) {
        sAcc[(i * 2 + 0) * 512 + is * 64 + rem] = acc[i][0];
        sAcc[(i * 2 + 1) * 512 + is * 64 + rem] = acc[i][1];
    }
    __syncthreads();
    if (is == 0) {
#pragma unroll
        for (int i = 0; i < 4; ++i) {
            ull s0 = 0ull, s1 = 0ull;
#pragma unroll
            for (int s = 0; s < 8; ++s) {
                s0 = add2(s0, sAcc[(i * 2 + 0) * 512 + s * 64 + rem]);
                s1 = add2(s1, sAcc[(i * 2 + 1) * 512 + s * 64 + rem]);
            }
            float* p = part + ((size_t)ip * 64 + bg * 4 + i) * 512 + j0 + jq * 4;
            *(ull*)p       = s0;
            *(ull*)(p + 2) = s1;
        }
    }
}

// ---------------------------------------------------------------------------
// Mega kernel: U-reduce -> z=U@Hc -> h=z@W1+b1 -> LN+ReLU -> out=r@W2+b2
// grid 128, 512 threads, grid barriers between stages.
// ---------------------------------------------------------------------------
__global__ void __launch_bounds__(512) mega_kernel(
    const float* __restrict__ Hc, const float* __restrict__ W1,
    const float* __restrict__ b1, const float* __restrict__ lnw,
    const float* __restrict__ lnb, const float* __restrict__ W2,
    const float* __restrict__ b2, float* __restrict__ out)
{
    __shared__ float sBuf[8192];   // 32 KB: staging + is-reduction scratch
    __shared__ float sWr[32];
    __shared__ float sStat[2];

    const int tid = threadIdx.x;
    const int gid = blockIdx.x * 512 + tid;

    // S0: reduce 16 chunk-partials -> g_U
    if (gid < 16384) {
        const int b = gid >> 8, e = gid & 255;
        const float4* p = (const float4*)(g_Up + (size_t)b * NCH * 1024) + e;
        float4 s = p[0];
#pragma unroll
        for (int ch = 1; ch < NCH; ++ch) {
            float4 v = p[ch * 256];
            s.x += v.x; s.y += v.y; s.z += v.z; s.w += v.w;
        }
        ((float4*)(g_U + (size_t)b * 1024))[e] = s;
    }
    grid_bar();

    // S1: z partials = U @ Hc
    gemm_stage<1024, 1>(g_U, Hc, g_pz, sBuf);
    grid_bar();

    // S2: h partials = z @ W1 (z-partials summed during staging)
    gemm_stage<512, 4>(g_pz, W1, g_ph, sBuf);
    grid_bar();

    // S3: reduce h-partials + bias, LayerNorm + ReLU -> g_r (blocks 0..63)
    if (blockIdx.x < 64) {
        const int b = blockIdx.x;
        float h = g_ph[(size_t)b * 512 + tid]
                + g_ph[((size_t)64  + b) * 512 + tid]
                + g_ph[((size_t)128 + b) * 512 + tid]
                + g_ph[((size_t)192 + b) * 512 + tid]
                + b1[tid];
        float ssum = h, ssq = h * h;
#pragma unroll
        for (int off = 16; off > 0; off >>= 1) {
            ssum += __shfl_xor_sync(0xffffffffu, ssum, off);
            ssq  += __shfl_xor_sync(0xffffffffu, ssq,  off);
        }
        if ((tid & 31) == 0) { sWr[tid >> 5] = ssum; sWr[16 + (tid >> 5)] = ssq; }
        __syncthreads();
        if (tid == 0) {
            float S = 0.f, Q = 0.f;
#pragma unroll
            for (int w = 0; w < 16; ++w) { S += sWr[w]; Q += sWr[16 + w]; }
            float mu  = S * (1.0f / 512.0f);
            float var = Q * (1.0f / 512.0f) - mu * mu;
            sStat[0] = mu;
            sStat[1] = rsqrtf(var + LN_EPS);
        }
        __syncthreads();
        float hn = (h - sStat[0]) * sStat[1] * lnw[tid] + lnb[tid];
        g_r[(size_t)b * 512 + tid] = fmaxf(hn, 0.0f);
    }
    grid_bar();

    // S4: out partials = r @ W2
    gemm_stage<512, 1>(g_r, W2, g_po, sBuf);
    grid_bar();

    // S5: reduce out-partials + bias -> out
    if (gid < 8192) {
        const int b = gid >> 7, q = gid & 127;
        float4 s = *(const float4*)(b2 + q * 4);
#pragma unroll
        for (int p = 0; p < 4; ++p) {
            float4 v = *(const float4*)(g_po + ((size_t)p * 64 + b) * 512 + q * 4);
            s.x += v.x; s.y += v.y; s.z += v.z; s.w += v.w;
        }
        *(float4*)(out + (size_t)b * 512 + q * 4) = s;
    }
}

extern "C" void kernel_launch(void* const* d_in, const int* in_sizes, int n_in,
                              void* d_out, int out_size)
{
    (void)in_sizes; (void)n_in; (void)out_size;
    cudaFuncSetAttribute(k1_kernel, cudaFuncAttributeMaxDynamicSharedMemorySize, 45056);

    const float* emb  = (const float*)d_in[0];
    const void*  mskp = d_in[1];
    const float* Bc   = (const float*)d_in[2];
    const float* Ac   = (const float*)d_in[3];
    const float* Hc   = (const float*)d_in[4];
    const float* W1   = (const float*)d_in[5];
    const float* b1   = (const float*)d_in[6];
    const float* lnw  = (const float*)d_in[7];
    const float* lnb  = (const float*)d_in[8];
    const float* W2   = (const float*)d_in[9];
    const float* b2   = (const float*)d_in[10];
    float* out = (float*)d_out;

    dim3 g1(NCH, NB);
    k1_kernel<<<g1, 256, 45056>>>(emb, mskp, Bc, Ac);
    mega_kernel<<<MBLOCKS, 512>>>(Hc, W1, b1, lnw, lnb, W2, b2, out);
}